// round 16
// baseline (speedup 1.0000x reference)
#include <cuda_runtime.h>
#include <cuda_fp16.h>
#include <math_constants.h>
#include <cstdint>

#define NB    16
#define CDIM  256
#define NPIX  4096
#define SPLITG 2                  // split-K for G
#define NROWS (NB * 512)          // 8192 k rows
#define NTILES_K1 32              // NPIX / 128

// ---------------------------------------------------------------------------
// scratch (device globals; allocation-free per harness rules)
// ---------------------------------------------------------------------------
__device__ __align__(16) __half g_xThi[(size_t)NB * NPIX * CDIM];   // xT[b][n][c] fp16
__device__ __align__(16) __half g_xh  [(size_t)NB * CDIM * NPIX];   // x[b][c][n] fp16
__device__ __align__(16) __half g_ekhi[(size_t)NB * 512 * NPIX];    // exp(k), no max shift
__device__ float g_partsum[(size_t)NTILES_K1 * NROWS];              // per-ntile row sums
__device__ __align__(16) __half g_part2[(size_t)NB * 512 * 512];    // fp16 [z][d][sp*256+c]
__device__ __align__(16) __half g_Udup[(size_t)4 * 256 * 512];      // U[h] duplicated in 2 col halves
__device__ __align__(16) __half g_W2h[NB * 256 * 512];
__device__ __align__(16) __half g_W3h[NB * 256 * 256];
__device__ __align__(16) __half g_wkhi[512 * 256];                  // Wk fp16 (w_qkv rows 512..1023)
__device__ __align__(16) __half g_wouth[256 * 512];
__device__ __align__(16) __half g_wqTh[256 * 512];                  // Wq^T [c][j] fp16
__device__ __align__(16) __half g_wvTh[256 * 512];                  // Wv^T [c][e] fp16

// ---------------------------------------------------------------------------
// helpers
// ---------------------------------------------------------------------------
__device__ __forceinline__ uint32_t smem_to_u32(const void* p) {
    uint32_t a;
    asm("{ .reg .u64 t; cvta.to.shared.u64 t, %1; cvt.u32.u64 %0, t; }" : "=r"(a) : "l"(p));
    return a;
}

#define LDMATRIX_X4(r, addr) \
    asm volatile("ldmatrix.sync.aligned.m8n8.x4.shared.b16 {%0,%1,%2,%3}, [%4];" \
        : "=r"((r)[0]), "=r"((r)[1]), "=r"((r)[2]), "=r"((r)[3]) : "r"(addr))

#define MMA_F16(d, a, b) \
    asm volatile("mma.sync.aligned.m16n8k16.row.col.f32.f16.f16.f32 " \
        "{%0,%1,%2,%3},{%4,%5,%6,%7},{%8,%9},{%0,%1,%2,%3};" \
        : "+f"((d)[0]), "+f"((d)[1]), "+f"((d)[2]), "+f"((d)[3]) \
        : "r"((a)[0]), "r"((a)[1]), "r"((a)[2]), "r"((a)[3]), \
          "r"((b)[0]), "r"((b)[1]))

#define CP_ASYNC16(saddr, gaddr) \
    asm volatile("cp.async.cg.shared.global [%0], [%1], 16;" :: "r"(saddr), "l"(gaddr))
#define CP_COMMIT()  asm volatile("cp.async.commit_group;")
#define CP_WAIT2()   asm volatile("cp.async.wait_group 2;")
#define CP_WAIT1()   asm volatile("cp.async.wait_group 1;")
#define CP_WAIT0()   asm volatile("cp.async.wait_group 0;")

// ---------------------------------------------------------------------------
// gmem -> smem stage loader: 2 tiles (A, B), each 128 rows x 64 fp16
// SW128-swizzled 128B rows; tile = 16KB, stage = 32KB, 3 stages.
// ---------------------------------------------------------------------------
__device__ __forceinline__ void load_stage(
    const __half* const* gt, const int* lds,
    uint32_t sb, int tid, int st, int kb)
{
    uint32_t base = sb + st * 32768;
    #pragma unroll
    for (int t = 0; t < 8; t++) {
        int i = tid + t * 256;
        int tile = i >> 10, idx = i & 1023, row = idx >> 3, seg = idx & 7;
        const __half* g = gt[tile] + (size_t)row * lds[tile] + kb + seg * 8;
        uint32_t off = (row << 7) + (seg << 4);
        off ^= (row & 7) << 4;
        CP_ASYNC16(base + tile * 16384 + off, g);
    }
    CP_COMMIT();
}

// ---------------------------------------------------------------------------
// fp16 GEMM via mma.sync: D[128,128] = A[128,K] x B[128,K]^T  (fp32 accum)
// 3-stage cp.async pipeline (2 chunks in flight across the per-chunk barrier).
// z split: zb = z / zdiv, zh = z % zdiv; operand base += zb*s?b + zh*s?h.
// ksplit_ntn > 0: blockIdx.x = ksp * ntn + ntile; koff = ksp*Ksub,
//                 C offset += ksp * sCsplit (element offset; buffer OR column).
// OUTMODE 0: fp32 out (+ optional bias).
// OUTMODE 1 (K1): ek = exp(acc) fp16 + per-row partial sums.
// OUTMODE 2: fp16 out (to Ch).
// OUTMODE 3: fp16 out scaled per OUTPUT COLUMN by 1/den[col], den computed
//            in-block from partsum rows zb*512 + zh*128 + col (fixed order).
// ---------------------------------------------------------------------------
template <int OUTMODE>
__global__ __launch_bounds__(256, 2) void mma_gemm(
    const __half* __restrict__ A, const __half* __restrict__ B,
    float* __restrict__ C, __half* __restrict__ Ch,
    float* __restrict__ partsum, const float* __restrict__ bias,
    int Ksub, int lda, int ldb, int ldc, int zdiv,
    long sAb, long sAh, long sBb, long sBh, long sCb, long sCh,
    int ksplit_ntn, long sCsplit)
{
    extern __shared__ __align__(128) char smem[];
    uint32_t sb = smem_to_u32(smem);
    const int tid = threadIdx.x, lane = tid & 31, wid = tid >> 5;
    const int wm = wid >> 1, wn = wid & 1;

    int ntile, koff; long coff;
    if (ksplit_ntn) {
        ntile = blockIdx.x % ksplit_ntn;
        int ksp = blockIdx.x / ksplit_ntn;
        koff = ksp * Ksub; coff = (long)ksp * sCsplit;
    } else { ntile = blockIdx.x; koff = 0; coff = 0; }
    const int m0 = blockIdx.y * 128;
    const int z  = blockIdx.z;
    const int zb = z / zdiv, zh = z - zb * zdiv;
    const long zoffC = zb * sCb + zh * sCh;

    const __half* gt[2];
    gt[0] = A + zb * sAb + zh * sAh + (long)m0 * lda + koff;
    gt[1] = B + zb * sBb + zh * sBh + (long)ntile * 128 * ldb + koff;
    int lds[2] = { lda, ldb };

    float acc[2][8][4];
    #pragma unroll
    for (int i = 0; i < 2; i++)
        #pragma unroll
        for (int j = 0; j < 8; j++)
            #pragma unroll
            for (int q = 0; q < 4; q++) acc[i][j][q] = 0.0f;

    const int nch = Ksub >> 6;     // >= 2 always
    load_stage(gt, lds, sb, tid, 0, 0);
    load_stage(gt, lds, sb, tid, 1, 64);

    int st = 0;
    for (int c = 0; c < nch; c++) {
        if (c + 2 < nch) {
            int st2 = st + 2; if (st2 >= 3) st2 -= 3;
            load_stage(gt, lds, sb, tid, st2, (c + 2) << 6);
            CP_WAIT2();
        } else if (c + 1 < nch) { CP_WAIT1(); }
        else { CP_WAIT0(); }
        __syncthreads();

        const uint32_t sA = sb + st * 32768;

        #pragma unroll
        for (int s = 0; s < 4; s++) {
            uint32_t ah[2][4];
            #pragma unroll
            for (int mt = 0; mt < 2; mt++) {
                int row = wm * 32 + mt * 16 + (lane & 15);
                uint32_t off = (row << 7) + s * 32 + ((lane >> 4) << 4);
                off ^= (row & 7) << 4;
                LDMATRIX_X4(ah[mt], sA + off);
            }
            uint32_t bh[4][4];
            #pragma unroll
            for (int np = 0; np < 4; np++) {
                int nrow = wn * 64 + np * 16 + ((lane >> 4) << 3) + (lane & 7);
                uint32_t off = (nrow << 7) + s * 32 + (((lane >> 3) & 1) << 4);
                off ^= (nrow & 7) << 4;
                LDMATRIX_X4(bh[np], sA + 16384 + off);
            }
            #pragma unroll
            for (int mt = 0; mt < 2; mt++)
                #pragma unroll
                for (int nt = 0; nt < 8; nt++)
                    MMA_F16(acc[mt][nt], ah[mt], &bh[nt >> 1][(nt & 1) * 2]);
        }
        __syncthreads();
        if (++st == 3) st = 0;
    }

    // -------- epilogue --------
    const int rbase = wm * 32 + (lane >> 2);
    const int cbase = wn * 64 + (lane & 3) * 2;

    if (OUTMODE == 0) {
        float* Cw = C + zoffC + coff + (long)m0 * ldc + (long)ntile * 128;
        #pragma unroll
        for (int mt = 0; mt < 2; mt++)
            #pragma unroll
            for (int nt = 0; nt < 8; nt++)
                #pragma unroll
                for (int hh = 0; hh < 2; hh++) {
                    int row = rbase + mt * 16 + hh * 8;
                    int col = cbase + nt * 8;
                    float v0 = acc[mt][nt][hh * 2 + 0];
                    float v1 = acc[mt][nt][hh * 2 + 1];
                    if (bias) { float bv = bias[m0 + row]; v0 += bv; v1 += bv; }
                    *(float2*)&Cw[(long)row * ldc + col] = make_float2(v0, v1);
                }
    } else if (OUTMODE == 2) {
        __half* Cw = Ch + zoffC + coff + (long)m0 * ldc + (long)ntile * 128;
        #pragma unroll
        for (int mt = 0; mt < 2; mt++)
            #pragma unroll
            for (int nt = 0; nt < 8; nt++)
                #pragma unroll
                for (int hh = 0; hh < 2; hh++) {
                    int row = rbase + mt * 16 + hh * 8;
                    int col = cbase + nt * 8;
                    __half2 p;
                    p.x = __float2half_rn(acc[mt][nt][hh * 2 + 0]);
                    p.y = __float2half_rn(acc[mt][nt][hh * 2 + 1]);
                    *(__half2*)&Cw[(long)row * ldc + col] = p;
                }
    } else if (OUTMODE == 3) {
        // fp16 out, scaled per output column by 1/den[col]
        float* rden = (float*)smem;   // stage smem fully drained
        if (tid < 128) {
            long rb = (long)zb * 512 + (long)zh * 128 + tid;
            float s = 0.0f;
            #pragma unroll
            for (int nt2 = 0; nt2 < NTILES_K1; nt2++)
                s += partsum[(long)nt2 * NROWS + rb];
            rden[tid] = 1.0f / s;
        }
        __syncthreads();
        __half* Cw = Ch + zoffC + coff + (long)m0 * ldc + (long)ntile * 128;
        #pragma unroll
        for (int mt = 0; mt < 2; mt++)
            #pragma unroll
            for (int nt = 0; nt < 8; nt++)
                #pragma unroll
                for (int hh = 0; hh < 2; hh++) {
                    int row = rbase + mt * 16 + hh * 8;
                    int col = cbase + nt * 8;
                    __half2 p;
                    p.x = __float2half_rn(acc[mt][nt][hh * 2 + 0] * rden[col + 0]);
                    p.y = __float2half_rn(acc[mt][nt][hh * 2 + 1] * rden[col + 1]);
                    *(__half2*)&Cw[(long)row * ldc + col] = p;
                }
    } else {
        // K1: ek = exp(acc) fp16 (no max shift; k ~ N(0,1), fp16 range safe)
        // + per-row partial sums -> deterministic partsum write
        __half* ek = Ch + zoffC + (long)m0 * ldc + (long)ntile * 128;
        float rs[2][2] = {{0.f, 0.f}, {0.f, 0.f}};
        #pragma unroll
        for (int mt = 0; mt < 2; mt++)
            #pragma unroll
            for (int nt = 0; nt < 8; nt++)
                #pragma unroll
                for (int hh = 0; hh < 2; hh++) {
                    int row = rbase + mt * 16 + hh * 8;
                    int col = cbase + nt * 8;
                    float e0 = __expf(acc[mt][nt][hh * 2 + 0]);
                    float e1 = __expf(acc[mt][nt][hh * 2 + 1]);
                    __half2 p; p.x = __float2half_rn(e0); p.y = __float2half_rn(e1);
                    *(__half2*)&ek[(long)row * ldc + col] = p;
                    rs[mt][hh] += e0 + e1;
                }
        float* red = (float*)smem;   // reuse stage smem (MMA loop fully drained)
        #pragma unroll
        for (int mt = 0; mt < 2; mt++)
            #pragma unroll
            for (int hh = 0; hh < 2; hh++) {
                float v = rs[mt][hh];
                v += __shfl_xor_sync(0xffffffffu, v, 1);
                v += __shfl_xor_sync(0xffffffffu, v, 2);
                if ((lane & 3) == 0)
                    red[wn * 128 + wm * 32 + mt * 16 + hh * 8 + (lane >> 2)] = v;
            }
        __syncthreads();
        if (tid < 128)
            partsum[(long)ntile * NROWS + (long)z * 512 + m0 + tid] = red[tid] + red[128 + tid];
    }
}

// ---------------------------------------------------------------------------
// prep (fused transpose + weights, one launch):
//   z < NB:  x[b][c][n] -> xT[b][n][c] fp16  AND  xh[b][c][n] fp16
//   z == NB: 512 weight blocks:
//     [0,128):   Wk cvt (w_qkv rows 512..1023) -> fp16
//     [128,256): w_out cvt -> fp16
//     [256,384): Wq transpose (rows 0..511)    -> WqT fp16 [c][j]
//     [384,512): Wv transpose (rows 1024..1535)-> WvT fp16 [c][e]
// ---------------------------------------------------------------------------
__global__ __launch_bounds__(256) void prep_kernel(
    const float* __restrict__ x,
    const float* __restrict__ w_qkv, const float* __restrict__ w_out)
{
    __shared__ float t[64][33];
    int tid = threadIdx.x;

    if (blockIdx.z < NB) {
        int b = blockIdx.z, c0 = blockIdx.y * 64, n0 = blockIdx.x * 32;
        const float* xp = x + ((size_t)b * CDIM + c0) * NPIX + n0;

        int rr = tid >> 3, col4 = (tid & 7) * 4;
        #pragma unroll
        for (int p = 0; p < 2; p++) {
            int c = rr + p * 32;
            float4 v = *(const float4*)&xp[(size_t)c * NPIX + col4];
            t[c][col4 + 0] = v.x; t[c][col4 + 1] = v.y;
            t[c][col4 + 2] = v.z; t[c][col4 + 3] = v.w;
            __half2 h0 = __floats2half2_rn(v.x, v.y);
            __half2 h1 = __floats2half2_rn(v.z, v.w);
            uint2 u; u.x = *(uint32_t*)&h0; u.y = *(uint32_t*)&h1;
            *(uint2*)&g_xh[((size_t)b * CDIM + c0 + c) * NPIX + n0 + col4] = u;
        }
        __syncthreads();

        size_t ob = ((size_t)b * NPIX + n0) * CDIM + c0;
        int nloc = tid >> 5, cp = (tid & 31) * 2;
        #pragma unroll
        for (int p = 0; p < 4; p++) {
            int n = nloc + p * 8;
            __half2 h;
            h.x = __float2half_rn(t[cp + 0][n]);
            h.y = __float2half_rn(t[cp + 1][n]);
            *(__half2*)&g_xThi[ob + (size_t)n * CDIM + cp] = h;
        }
        return;
    }

    // weight blocks: blk in [0, 512)
    int blk = blockIdx.y * 128 + blockIdx.x;
    if (blk < 128) {
        int i = blk * 256 + tid;                  // 32768 float4s (Wk rows 512..1023)
        float4 v = ((const float4*)(w_qkv + 512 * 256))[i];
        __half2 a = __floats2half2_rn(v.x, v.y);
        __half2 b = __floats2half2_rn(v.z, v.w);
        ((__half2*)g_wkhi)[i * 2 + 0] = a;
        ((__half2*)g_wkhi)[i * 2 + 1] = b;
    } else if (blk < 256) {
        int i = (blk - 128) * 256 + tid;          // 32768 float4s
        float4 v = ((const float4*)w_out)[i];
        __half2 a = __floats2half2_rn(v.x, v.y);
        __half2 b = __floats2half2_rn(v.z, v.w);
        ((__half2*)g_wouth)[i * 2 + 0] = a;
        ((__half2*)g_wouth)[i * 2 + 1] = b;
    } else {
        // transpose tiles: 128 per weight; Wq (rows 0..511) or Wv (rows 1024..1535)
        int tnum = blk & 127;                     // 16 j-tiles x 8 c-tiles
        const float* src = (blk < 384) ? w_qkv : (w_qkv + 1024 * 256);
        __half* dst = (blk < 384) ? g_wqTh : g_wvTh;
        int j0 = (tnum >> 3) * 32, c0 = (tnum & 7) * 32;
        int r = tid >> 5, cn = tid & 31;
        #pragma unroll
        for (int p = 0; p < 4; p++)
            t[r + p * 8][cn] = src[(size_t)(j0 + r + p * 8) * 256 + c0 + cn];
        __syncthreads();
        #pragma unroll
        for (int p = 0; p < 4; p++) {
            int c = r + p * 8;
            dst[(size_t)(c0 + c) * 512 + j0 + cn] = __float2half_rn(t[cn][c]);
        }
    }
}

// ---------------------------------------------------------------------------
extern "C" void kernel_launch(void* const* d_in, const int* in_sizes, int n_in,
                              void* d_out, int out_size)
{
    const float* x     = (const float*)d_in[0];
    const float* w_qkv = (const float*)d_in[1];
    const float* w_out = (const float*)d_in[2];
    const float* b_out = (const float*)d_in[3];
    float* y = (float*)d_out;

    float* p_partsum;
    __half *p_xThi, *p_xh, *p_ekhi, *p_wkhi, *p_wouth, *p_wqTh, *p_wvTh;
    __half *p_part2, *p_Udup, *p_W2h, *p_W3h;
    cudaGetSymbolAddress((void**)&p_partsum, g_partsum);
    cudaGetSymbolAddress((void**)&p_xThi, g_xThi);
    cudaGetSymbolAddress((void**)&p_xh, g_xh);
    cudaGetSymbolAddress((void**)&p_ekhi, g_ekhi);
    cudaGetSymbolAddress((void**)&p_wkhi, g_wkhi);
    cudaGetSymbolAddress((void**)&p_wouth, g_wouth);
    cudaGetSymbolAddress((void**)&p_wqTh, g_wqTh);
    cudaGetSymbolAddress((void**)&p_wvTh, g_wvTh);
    cudaGetSymbolAddress((void**)&p_part2, g_part2);
    cudaGetSymbolAddress((void**)&p_Udup, g_Udup);
    cudaGetSymbolAddress((void**)&p_W2h, g_W2h);
    cudaGetSymbolAddress((void**)&p_W3h, g_W3h);

    const int SMEM_GEMM = 3 * 32768;   // 96 KB, 3 stages
    cudaFuncSetAttribute(mma_gemm<0>, cudaFuncAttributeMaxDynamicSharedMemorySize, SMEM_GEMM);
    cudaFuncSetAttribute(mma_gemm<1>, cudaFuncAttributeMaxDynamicSharedMemorySize, SMEM_GEMM);
    cudaFuncSetAttribute(mma_gemm<2>, cudaFuncAttributeMaxDynamicSharedMemorySize, SMEM_GEMM);
    cudaFuncSetAttribute(mma_gemm<3>, cudaFuncAttributeMaxDynamicSharedMemorySize, SMEM_GEMM);

    dim3 t(256);

    // 1) fused prep: xT fp16 + xh fp16 + weights (Wk, w_out, WqT, WvT)
    prep_kernel<<<dim3(NPIX / 32, CDIM / 64, NB + 1), t>>>(x, w_qkv, w_out);

    // 2) Udup[h] = w_out_h @ Wv_h, written twice (column halves 0 and 256).
    //    z = h*2 + copy: zb=h (A,B,C h-blocks), zh=copy (C column offset 256).
    mma_gemm<2><<<dim3(2, 2, 8), t, SMEM_GEMM>>>(
        p_wouth, p_wvTh,
        nullptr, p_Udup, nullptr, nullptr,
        128, 512, 512, 512, 2,
        128L, 0L, 128L, 0L, 256L * 512, 256L,
        0, 0L);

    // 3) K1 (k half only): ek = exp(Wk @ x) fp16 + row partial sums
    mma_gemm<1><<<dim3(NTILES_K1, 4, NB), t, SMEM_GEMM>>>(
        p_wkhi, p_xThi,
        nullptr, p_ekhi, p_partsum, nullptr,
        256, 256, 256, NPIX, 1,
        0L, 0L, (long)NPIX * CDIM, 0L, 512L * NPIX, 0L,
        0, 0L);

    // 4) G: part2[z][d][sp*256 + c] = ek-chunk @ xh-chunk^T
    //    (split-K=2; splits land in adjacent 256-column halves of one row)
    mma_gemm<2><<<dim3(SPLITG * 2, 4, NB), t, SMEM_GEMM>>>(
        p_ekhi, p_xh,
        nullptr, p_part2, nullptr, nullptr,
        NPIX / SPLITG, NPIX, NPIX, 512, 1,
        512L * NPIX, 0L, (long)CDIM * NPIX, 0L, 512L * 512, 0L,
        2, 256L);

    // 5) w2' (mma, K=512 over both split halves; split reduction inside MMA):
    //    W2h[b][o][h*128+d] = (sum_k Udup[h][o][k] * part2[b][h*128+d][k]) / den[d]
    mma_gemm<3><<<dim3(1, 2, 64), t, SMEM_GEMM>>>(
        p_Udup, p_part2,
        nullptr, p_W2h, p_partsum, nullptr,
        512, 512, 512, 512, 4,
        0L, 256L * 512, 512L * 512, 128L * 512, 256L * 512, 128L,
        0, 0L);

    // 6) K4b (mma): W3h[b] = W2h[b] @ WqT^T
    mma_gemm<2><<<dim3(2, 2, NB), t, SMEM_GEMM>>>(
        p_W2h, p_wqTh,
        nullptr, p_W3h, nullptr, nullptr,
        512, 512, 512, 256, 1,
        256L * 512, 0L, 0L, 0L, 256L * 256, 0L,
        0, 0L);

    // 7) K5: y[b] = W3[b] @ x[b] + b_out
    mma_gemm<0><<<dim3(32, 2, NB), t, SMEM_GEMM>>>(
        p_W3h, p_xThi,
        y, nullptr, nullptr, b_out,
        256, 256, 256, NPIX, 1,
        256L * 256, 0L, (long)NPIX * CDIM, 0L, (long)CDIM * NPIX, 0L,
        0, 0L);
}